// round 2
// baseline (speedup 1.0000x reference)
#include <cuda_runtime.h>
#include <math.h>

// Problem constants (fixed shapes per reference)
#define D   32      // latent dim
#define HH  64      // hidden
#define BB  8192    // batch
#define TT  256     // time steps
#define MT  64      // batch rows per CTA  (128 CTAs * 64 = 8192 exactly)
#define ZSD 132     // row stride (floats) for dup'd Z   [D][2*MT + pad]
#define HSD 132     // row stride (floats) for dup'd H   [H][2*MT + pad]

// Shared layout (float offsets)
//  sW1 : 33*64 = 2112   @ 0
//  sW2 : 64*64 = 4096   @ 2112
//  sW3 : 64*32 = 2048   @ 6208
//  sb1 : 64             @ 8256
//  sb2 : 64             @ 8320
//  sb3 : 32             @ 8384
//  sstd: 32             @ 8416
//  sTs : 256            @ 8448
//  sZd : 32*132 = 4224  @ 8704   (duplicated: [d][2m] = {z,z})
//  sH1d: 64*132 = 8448  @ 12928
//  sH2d: 64*132 = 8448  @ 21376
//  total 29824 floats = 119296 bytes
#define SMEM_FLOATS 29824

typedef unsigned long long u64;

__device__ __forceinline__ u64 ffma2(u64 a, u64 b, u64 c) {
    u64 d;
    asm("fma.rn.f32x2 %0, %1, %2, %3;" : "=l"(d) : "l"(a), "l"(b), "l"(c));
    return d;
}
__device__ __forceinline__ u64 fmul2(u64 a, u64 b) {
    u64 d;
    asm("mul.rn.f32x2 %0, %1, %2;" : "=l"(d) : "l"(a), "l"(b));
    return d;
}
__device__ __forceinline__ u64 pk(float x, float y) {
    u64 r;
    asm("mov.b64 %0, {%1, %2};" : "=l"(r) : "f"(x), "f"(y));
    return r;
}
__device__ __forceinline__ float2 unpk(u64 v) {
    float2 r;
    asm("mov.b64 {%0, %1}, %2;" : "=f"(r.x), "=f"(r.y) : "l"(v));
    return r;
}
__device__ __forceinline__ float tanha(float x) {
    float y;
    asm("tanh.approx.f32 %0, %1;" : "=f"(y) : "f"(x));
    return y;
}

__global__ __launch_bounds__(256, 1)
void sde_kernel(const float* __restrict__ z0,
                const float* __restrict__ ts,
                const float* __restrict__ dW,
                const float* __restrict__ W1, const float* __restrict__ b1,
                const float* __restrict__ W2, const float* __restrict__ b2,
                const float* __restrict__ W3, const float* __restrict__ b3,
                const float* __restrict__ logstd,
                float* __restrict__ out)
{
    extern __shared__ float sm[];
    float* sW1  = sm;
    float* sW2  = sm + 2112;
    float* sW3  = sm + 6208;
    float* sb1  = sm + 8256;
    float* sb2  = sm + 8320;
    float* sb3  = sm + 8384;
    float* sstd = sm + 8416;
    float* sTs  = sm + 8448;
    float* sZd  = sm + 8704;
    float* sH1d = sm + 12928;
    float* sH2d = sm + 21376;

    const int tid = threadIdx.x;
    const int tx = tid & 15;        // output-column block
    const int ty = tid >> 4;        // row block
    const int m0 = ty * 4;
    const int j0 = tx * 4;          // GEMM1/2: 4 cols per thread (2 packed pairs)
    const int d0 = tx * 2;          // GEMM3: 2 cols per thread (1 packed pair)
    const int base = blockIdx.x * MT;

    // ---- one-time parameter staging ----
    for (int i = tid; i < 33 * HH; i += 256) sW1[i] = W1[i];
    for (int i = tid; i < HH * HH; i += 256) sW2[i] = W2[i];
    for (int i = tid; i < HH * D;  i += 256) sW3[i] = W3[i];
    if (tid < HH) { sb1[tid] = b1[tid]; sb2[tid] = b2[tid]; }
    if (tid < D)  { sb3[tid] = b3[tid]; sstd[tid] = expf(logstd[tid]); }
    sTs[tid] = ts[tid];   // TT == 256 == blockDim
    __syncthreads();

    // ---- hoisted per-thread constants (packed) ----
    u64 bias1[2], bias2[2], bias3, w0p[2], s2base;
    {
        ulonglong2 t1 = *(const ulonglong2*)&sb1[j0];
        bias1[0] = t1.x; bias1[1] = t1.y;
        ulonglong2 t2 = *(const ulonglong2*)&sb2[j0];
        bias2[0] = t2.x; bias2[1] = t2.y;
        bias3 = *(const u64*)&sb3[d0];
        ulonglong2 t3 = *(const ulonglong2*)&sW1[j0];     // t-row of W1
        w0p[0] = t3.x; w0p[1] = t3.y;
        s2base = pk(sstd[d0], sstd[d0 + 1]);
    }

    // ---- z0 -> registers (col-packed), out[0], and dup'd sZd ----
    u64 zreg[4];
    #pragma unroll
    for (int mi = 0; mi < 4; mi++) {
        const int m = m0 + mi;
        zreg[mi] = *(const u64*)&z0[(size_t)(base + m) * D + d0];
        *(u64*)&out[(size_t)(base + m) * D + d0] = zreg[mi];
        float2 zz = unpk(zreg[mi]);
        *(u64*)&sZd[d0 * ZSD + 2 * m]       = pk(zz.x, zz.x);
        *(u64*)&sZd[(d0 + 1) * ZSD + 2 * m] = pk(zz.y, zz.y);
    }
    __syncthreads();

    // ---- time loop (sequential; all state stays in smem/regs) ----
    for (int t = 0; t < TT - 1; ++t) {
        const float tcur = sTs[t];
        const float dtv  = sTs[t + 1] - tcur;
        const float sq   = sqrtf(dtv);

        // prefetch this step's noise early; consumed at end of step
        u64 dwv[4];
        {
            const float* dwp = dW + ((size_t)t * BB + base + m0) * D + d0;
            #pragma unroll
            for (int mi = 0; mi < 4; mi++)
                dwv[mi] = *(const u64*)(dwp + (size_t)mi * D);
        }

        // ============ GEMM1: [t,z] @ W1 -> tanh -> sH1d (dup'd) ============
        {
            u64 acc[4][2];
            {
                u64 t2 = pk(tcur, tcur);
                u64 i01 = ffma2(t2, w0p[0], bias1[0]);
                u64 i23 = ffma2(t2, w0p[1], bias1[1]);
                #pragma unroll
                for (int mi = 0; mi < 4; mi++) { acc[mi][0] = i01; acc[mi][1] = i23; }
            }
            #pragma unroll 8
            for (int k = 0; k < D; k++) {
                ulonglong2 a0 = *(const ulonglong2*)&sZd[k * ZSD + 2 * m0];      // rows m0,m0+1 (dup'd)
                ulonglong2 a1 = *(const ulonglong2*)&sZd[k * ZSD + 2 * m0 + 4];  // rows m0+2,m0+3
                ulonglong2 bv = *(const ulonglong2*)&sW1[(k + 1) * HH + j0];     // col pairs
                acc[0][0] = ffma2(a0.x, bv.x, acc[0][0]); acc[0][1] = ffma2(a0.x, bv.y, acc[0][1]);
                acc[1][0] = ffma2(a0.y, bv.x, acc[1][0]); acc[1][1] = ffma2(a0.y, bv.y, acc[1][1]);
                acc[2][0] = ffma2(a1.x, bv.x, acc[2][0]); acc[2][1] = ffma2(a1.x, bv.y, acc[2][1]);
                acc[3][0] = ffma2(a1.y, bv.x, acc[3][0]); acc[3][1] = ffma2(a1.y, bv.y, acc[3][1]);
            }
            #pragma unroll
            for (int jp = 0; jp < 2; ++jp) {
                float2 r0 = unpk(acc[0][jp]);
                float2 r1 = unpk(acc[1][jp]);
                float2 r2 = unpk(acc[2][jp]);
                float2 r3 = unpk(acc[3][jp]);
                // column j0+2jp (lane .x), rows m0..m0+3, stored duplicated
                float a0 = tanha(r0.x), a1 = tanha(r1.x), a2 = tanha(r2.x), a3 = tanha(r3.x);
                ulonglong2 s;
                s.x = pk(a0, a0); s.y = pk(a1, a1);
                *(ulonglong2*)&sH1d[(j0 + 2 * jp) * HSD + 2 * m0] = s;
                s.x = pk(a2, a2); s.y = pk(a3, a3);
                *(ulonglong2*)&sH1d[(j0 + 2 * jp) * HSD + 2 * m0 + 4] = s;
                // column j0+2jp+1 (lane .y)
                float c0 = tanha(r0.y), c1 = tanha(r1.y), c2 = tanha(r2.y), c3 = tanha(r3.y);
                s.x = pk(c0, c0); s.y = pk(c1, c1);
                *(ulonglong2*)&sH1d[(j0 + 2 * jp + 1) * HSD + 2 * m0] = s;
                s.x = pk(c2, c2); s.y = pk(c3, c3);
                *(ulonglong2*)&sH1d[(j0 + 2 * jp + 1) * HSD + 2 * m0 + 4] = s;
            }
        }
        __syncthreads();

        // ============ GEMM2: h1 @ W2 -> tanh -> sH2d (dup'd) ============
        {
            u64 acc[4][2];
            #pragma unroll
            for (int mi = 0; mi < 4; mi++) { acc[mi][0] = bias2[0]; acc[mi][1] = bias2[1]; }
            #pragma unroll 8
            for (int k = 0; k < HH; k++) {
                ulonglong2 a0 = *(const ulonglong2*)&sH1d[k * HSD + 2 * m0];
                ulonglong2 a1 = *(const ulonglong2*)&sH1d[k * HSD + 2 * m0 + 4];
                ulonglong2 bv = *(const ulonglong2*)&sW2[k * HH + j0];
                acc[0][0] = ffma2(a0.x, bv.x, acc[0][0]); acc[0][1] = ffma2(a0.x, bv.y, acc[0][1]);
                acc[1][0] = ffma2(a0.y, bv.x, acc[1][0]); acc[1][1] = ffma2(a0.y, bv.y, acc[1][1]);
                acc[2][0] = ffma2(a1.x, bv.x, acc[2][0]); acc[2][1] = ffma2(a1.x, bv.y, acc[2][1]);
                acc[3][0] = ffma2(a1.y, bv.x, acc[3][0]); acc[3][1] = ffma2(a1.y, bv.y, acc[3][1]);
            }
            #pragma unroll
            for (int jp = 0; jp < 2; ++jp) {
                float2 r0 = unpk(acc[0][jp]);
                float2 r1 = unpk(acc[1][jp]);
                float2 r2 = unpk(acc[2][jp]);
                float2 r3 = unpk(acc[3][jp]);
                float a0 = tanha(r0.x), a1 = tanha(r1.x), a2 = tanha(r2.x), a3 = tanha(r3.x);
                ulonglong2 s;
                s.x = pk(a0, a0); s.y = pk(a1, a1);
                *(ulonglong2*)&sH2d[(j0 + 2 * jp) * HSD + 2 * m0] = s;
                s.x = pk(a2, a2); s.y = pk(a3, a3);
                *(ulonglong2*)&sH2d[(j0 + 2 * jp) * HSD + 2 * m0 + 4] = s;
                float c0 = tanha(r0.y), c1 = tanha(r1.y), c2 = tanha(r2.y), c3 = tanha(r3.y);
                s.x = pk(c0, c0); s.y = pk(c1, c1);
                *(ulonglong2*)&sH2d[(j0 + 2 * jp + 1) * HSD + 2 * m0] = s;
                s.x = pk(c2, c2); s.y = pk(c3, c3);
                *(ulonglong2*)&sH2d[(j0 + 2 * jp + 1) * HSD + 2 * m0 + 4] = s;
            }
        }
        __syncthreads();

        // ========= GEMM3: h2 @ W3 + fused Euler-Maruyama update =========
        {
            u64 acc[4];
            #pragma unroll
            for (int mi = 0; mi < 4; mi++) acc[mi] = bias3;
            #pragma unroll 8
            for (int k = 0; k < HH; k++) {
                ulonglong2 a0 = *(const ulonglong2*)&sH2d[k * HSD + 2 * m0];
                ulonglong2 a1 = *(const ulonglong2*)&sH2d[k * HSD + 2 * m0 + 4];
                u64 bv = *(const u64*)&sW3[k * D + d0];
                acc[0] = ffma2(a0.x, bv, acc[0]);
                acc[1] = ffma2(a0.y, bv, acc[1]);
                acc[2] = ffma2(a1.x, bv, acc[2]);
                acc[3] = ffma2(a1.y, bv, acc[3]);
            }
            u64 dt2 = pk(dtv, dtv);
            u64 s2  = fmul2(s2base, pk(sq, sq));
            float* orow = out + ((size_t)(t + 1) * BB + base + m0) * D + d0;
            #pragma unroll
            for (int mi = 0; mi < 4; mi++) {
                zreg[mi] = ffma2(acc[mi], dt2, ffma2(s2, dwv[mi], zreg[mi]));
                *(u64*)(orow + (size_t)mi * D) = zreg[mi];
                float2 zz = unpk(zreg[mi]);
                const int m = m0 + mi;
                *(u64*)&sZd[d0 * ZSD + 2 * m]       = pk(zz.x, zz.x);
                *(u64*)&sZd[(d0 + 1) * ZSD + 2 * m] = pk(zz.y, zz.y);
            }
        }
        __syncthreads();   // sZd writes visible before next step's GEMM1
    }
}

extern "C" void kernel_launch(void* const* d_in, const int* in_sizes, int n_in,
                              void* d_out, int out_size)
{
    (void)in_sizes; (void)n_in; (void)out_size;
    const float* z0     = (const float*)d_in[0];
    const float* ts     = (const float*)d_in[1];
    const float* dW     = (const float*)d_in[2];
    const float* W1     = (const float*)d_in[3];
    const float* b1     = (const float*)d_in[4];
    const float* W2     = (const float*)d_in[5];
    const float* b2     = (const float*)d_in[6];
    const float* W3     = (const float*)d_in[7];
    const float* b3     = (const float*)d_in[8];
    const float* logstd = (const float*)d_in[9];
    float* out = (float*)d_out;

    static bool attr_set = false;  // idempotent attribute; not a work guard
    if (!attr_set) {
        cudaFuncSetAttribute(sde_kernel,
                             cudaFuncAttributeMaxDynamicSharedMemorySize,
                             SMEM_FLOATS * sizeof(float));
        attr_set = true;
    }

    sde_kernel<<<BB / MT, 256, SMEM_FLOATS * sizeof(float)>>>(
        z0, ts, dW, W1, b1, W2, b2, W3, b3, logstd, out);
}

// round 4
// speedup vs baseline: 1.1572x; 1.1572x over previous
#include <cuda_runtime.h>
#include <math.h>

#define D   32
#define HH  64
#define BB  8192
#define TT  256
#define MT  64      // rows per CTA; 128 CTAs
// 128 threads: tx = tid&15 (16 col-blocks), ty = tid>>4 (8 row-blocks of 8)

// smem float offsets
#define O_W1D 0              // 33*128 dup'd swizzled
#define O_W2D 4224           // 64*128
#define O_W3D 12416          // 64*64
#define O_B1D 16512          // 128 dup'd
#define O_B2D 16640
#define O_B3D 16768          // 64 dup'd
#define O_STD 16832          // 32
#define O_TS  16864          // 256
#define O_Z   17120          // 32*64 rotated
#define O_H1  19168          // 64*64 rotated
#define O_H2  23264          // 64*64 rotated
#define SMEM_FLOATS 27360

typedef unsigned long long u64;

__device__ __forceinline__ u64 ffma2(u64 a, u64 b, u64 c) {
    u64 d; asm("fma.rn.f32x2 %0, %1, %2, %3;" : "=l"(d) : "l"(a), "l"(b), "l"(c)); return d;
}
__device__ __forceinline__ u64 fmul2(u64 a, u64 b) {
    u64 d; asm("mul.rn.f32x2 %0, %1, %2;" : "=l"(d) : "l"(a), "l"(b)); return d;
}
__device__ __forceinline__ u64 pk(float x, float y) {
    u64 r; asm("mov.b64 %0, {%1, %2};" : "=l"(r) : "f"(x), "f"(y)); return r;
}
__device__ __forceinline__ float2 unpk(u64 v) {
    float2 r; asm("mov.b64 {%0, %1}, %2;" : "=f"(r.x), "=f"(r.y) : "l"(v)); return r;
}
__device__ __forceinline__ float tanha(float x) {
    float y; asm("tanh.approx.f32 %0, %1;" : "=f"(y) : "f"(x)); return y;
}

union F4U { float4 f; u64 u[2]; };

__device__ __forceinline__ F4U ld4(const float* p) {
    F4U r; r.f = *(const float4*)p; return r;
}

__global__ __launch_bounds__(128, 1)
void sde_kernel(const float* __restrict__ z0,
                const float* __restrict__ ts,
                const float* __restrict__ dW,
                const float* __restrict__ W1, const float* __restrict__ b1,
                const float* __restrict__ W2, const float* __restrict__ b2,
                const float* __restrict__ W3, const float* __restrict__ b3,
                const float* __restrict__ logstd,
                float* __restrict__ out)
{
    extern __shared__ float sm[];
    float* sW1d = sm + O_W1D;
    float* sW2d = sm + O_W2D;
    float* sW3d = sm + O_W3D;
    float* sb1d = sm + O_B1D;
    float* sb2d = sm + O_B2D;
    float* sb3d = sm + O_B3D;
    float* sstd = sm + O_STD;
    float* sTs  = sm + O_TS;
    float* sZ   = sm + O_Z;
    float* sH1  = sm + O_H1;
    float* sH2  = sm + O_H2;

    const int tid = threadIdx.x;
    const int tx  = tid & 15;
    const int ty  = tid >> 4;
    const int ty2 = ty * 2;
    const int m0  = ty * 8;
    const int j0  = tx * 4;
    const int d0  = tx * 2;
    const int base = blockIdx.x * MT;

    // ---- staging: weights duplicated ({w,w} adjacent), 16B-unit swizzled ----
    for (int i = tid; i < 33 * 128; i += 128) {
        int row = i >> 7, f = i & 127;
        int u = f >> 2, us = u ^ ((u >> 3) & 1);
        sW1d[(row << 7) + (us << 2) + (f & 3)] = W1[(row << 6) + (f >> 1)];
    }
    for (int i = tid; i < 64 * 128; i += 128) {
        int row = i >> 7, f = i & 127;
        int u = f >> 2, us = u ^ ((u >> 3) & 1);
        sW2d[(row << 7) + (us << 2) + (f & 3)] = W2[(row << 6) + (f >> 1)];
    }
    for (int i = tid; i < 64 * 64; i += 128) {
        int row = i >> 6, f = i & 63;
        sW3d[(row << 6) + f] = W3[(row << 5) + (f >> 1)];
    }
    if (tid < 128) { sb1d[tid] = b1[tid >> 1]; sb2d[tid] = b2[tid >> 1]; }
    if (tid < 64)  { sb3d[tid] = b3[tid >> 1]; }
    if (tid < 32)  { sstd[tid] = expf(logstd[tid]); }
    sTs[tid] = ts[tid]; sTs[tid + 128] = ts[tid + 128];
    __syncthreads();

    // ---- hoisted per-thread constants & offsets ----
    // B (dup'd weight) offsets within a 128-float row, swizzled
    const int u0 = 2 * tx, u1 = 2 * tx + 1;
    const int ob0 = (u0 ^ ((u0 >> 3) & 1)) << 2;
    const int ob1 = (u1 ^ ((u1 >> 3) & 1)) << 2;
    // activation STS offsets (rotation by col>>2)
    const int osH0 = ((ty2 + tx) & 15) << 2;
    const int osH1 = ((ty2 + 1 + tx) & 15) << 2;
    const int osZ0 = ((ty2 + (tx >> 1)) & 15) << 2;
    const int osZ1 = ((ty2 + 1 + (tx >> 1)) & 15) << 2;

    u64 bc1[4], bc2[4], bc3[2], w1t[4];
    {
        F4U t;
        t = ld4(sb1d + 8 * tx);     bc1[0] = t.u[0]; bc1[1] = t.u[1];
        t = ld4(sb1d + 8 * tx + 4); bc1[2] = t.u[0]; bc1[3] = t.u[1];
        t = ld4(sb2d + 8 * tx);     bc2[0] = t.u[0]; bc2[1] = t.u[1];
        t = ld4(sb2d + 8 * tx + 4); bc2[2] = t.u[0]; bc2[3] = t.u[1];
        t = ld4(sb3d + 4 * tx);     bc3[0] = t.u[0]; bc3[1] = t.u[1];
        t = ld4(sW1d + ob0);        w1t[0] = t.u[0]; w1t[1] = t.u[1];   // t-row, cols j0..j0+1
        t = ld4(sW1d + ob1);        w1t[2] = t.u[0]; w1t[3] = t.u[1];   // cols j0+2..j0+3
    }
    const u64 s2base = pk(sstd[d0], sstd[d0 + 1]);

    // ---- z init: registers (col-packed per row), out[0], rotated sZ ----
    u64 zp[8];
    #pragma unroll
    for (int r = 0; r < 8; r++) {
        zp[r] = *(const u64*)&z0[(size_t)(base + m0 + r) * D + d0];
        *(u64*)&out[(size_t)(base + m0 + r) * D + d0] = zp[r];
    }
    #pragma unroll
    for (int c = 0; c < 2; c++) {
        float4 lo, hi;
        lo.x = unpk(zp[0]).x; lo.y = unpk(zp[1]).x; lo.z = unpk(zp[2]).x; lo.w = unpk(zp[3]).x;
        hi.x = unpk(zp[4]).x; hi.y = unpk(zp[5]).x; hi.z = unpk(zp[6]).x; hi.w = unpk(zp[7]).x;
        if (c == 1) {
            lo.x = unpk(zp[0]).y; lo.y = unpk(zp[1]).y; lo.z = unpk(zp[2]).y; lo.w = unpk(zp[3]).y;
            hi.x = unpk(zp[4]).y; hi.y = unpk(zp[5]).y; hi.z = unpk(zp[6]).y; hi.w = unpk(zp[7]).y;
        }
        float* p = sZ + (d0 + c) * 64;
        *(float4*)(p + osZ0) = lo;
        *(float4*)(p + osZ1) = hi;
    }
    __syncthreads();

    // ==================== time loop ====================
    for (int t = 0; t < TT - 1; ++t) {
        const float tcur = sTs[t];
        const float dtv  = sTs[t + 1] - tcur;
        const float sq   = sqrtf(dtv);

        // prefetch noise (consumed in epilogue3)
        u64 dwv[8];
        {
            const float* dwp = dW + ((size_t)t * BB + base + m0) * D + d0;
            #pragma unroll
            for (int r = 0; r < 8; r++) dwv[r] = *(const u64*)(dwp + (size_t)r * D);
        }

        u64 acc[4][4];

        // ---------- GEMM1: [t,z] @ W1 ----------
        {
            u64 t2 = pk(tcur, tcur);
            u64 i0 = ffma2(t2, w1t[0], bc1[0]);
            u64 i1 = ffma2(t2, w1t[1], bc1[1]);
            u64 i2 = ffma2(t2, w1t[2], bc1[2]);
            u64 i3 = ffma2(t2, w1t[3], bc1[3]);
            #pragma unroll
            for (int p = 0; p < 4; p++) { acc[p][0] = i0; acc[p][1] = i1; acc[p][2] = i2; acc[p][3] = i3; }

            for (int k4 = 0; k4 < 8; ++k4) {
                const int oa0 = ((ty2 + k4) & 15) << 2;
                const int oa1 = ((ty2 + 1 + k4) & 15) << 2;
                const float* arow = sZ + k4 * 256;
                const float* wrow = sW1d + (k4 * 4 + 1) * 128;
                #pragma unroll
                for (int kk = 0; kk < 4; ++kk) {
                    F4U a0 = ld4(arow + kk * 64 + oa0);
                    F4U a1 = ld4(arow + kk * 64 + oa1);
                    F4U b0 = ld4(wrow + kk * 128 + ob0);
                    F4U b1v = ld4(wrow + kk * 128 + ob1);
                    #pragma unroll
                    for (int c = 0; c < 4; c++) {
                        u64 bv = (c < 2) ? b0.u[c] : b1v.u[c - 2];
                        acc[0][c] = ffma2(a0.u[0], bv, acc[0][c]);
                        acc[1][c] = ffma2(a0.u[1], bv, acc[1][c]);
                        acc[2][c] = ffma2(a1.u[0], bv, acc[2][c]);
                        acc[3][c] = ffma2(a1.u[1], bv, acc[3][c]);
                    }
                }
            }
            // epilogue -> sH1 (tanh, rotated layout)
            #pragma unroll
            for (int c = 0; c < 4; c++) {
                float2 r0 = unpk(acc[0][c]), r1 = unpk(acc[1][c]);
                float2 r2 = unpk(acc[2][c]), r3 = unpk(acc[3][c]);
                float4 lo, hi;
                lo.x = tanha(r0.x); lo.y = tanha(r0.y); lo.z = tanha(r1.x); lo.w = tanha(r1.y);
                hi.x = tanha(r2.x); hi.y = tanha(r2.y); hi.z = tanha(r3.x); hi.w = tanha(r3.y);
                float* p = sH1 + (j0 + c) * 64;
                *(float4*)(p + osH0) = lo;
                *(float4*)(p + osH1) = hi;
            }
        }
        __syncthreads();

        // ---------- GEMM2: h1 @ W2 ----------
        {
            #pragma unroll
            for (int p = 0; p < 4; p++) { acc[p][0] = bc2[0]; acc[p][1] = bc2[1]; acc[p][2] = bc2[2]; acc[p][3] = bc2[3]; }

            for (int k4 = 0; k4 < 16; ++k4) {
                const int oa0 = ((ty2 + k4) & 15) << 2;
                const int oa1 = ((ty2 + 1 + k4) & 15) << 2;
                const float* arow = sH1 + k4 * 256;
                const float* wrow = sW2d + k4 * 512;
                #pragma unroll
                for (int kk = 0; kk < 4; ++kk) {
                    F4U a0 = ld4(arow + kk * 64 + oa0);
                    F4U a1 = ld4(arow + kk * 64 + oa1);
                    F4U b0 = ld4(wrow + kk * 128 + ob0);
                    F4U b1v = ld4(wrow + kk * 128 + ob1);
                    #pragma unroll
                    for (int c = 0; c < 4; c++) {
                        u64 bv = (c < 2) ? b0.u[c] : b1v.u[c - 2];
                        acc[0][c] = ffma2(a0.u[0], bv, acc[0][c]);
                        acc[1][c] = ffma2(a0.u[1], bv, acc[1][c]);
                        acc[2][c] = ffma2(a1.u[0], bv, acc[2][c]);
                        acc[3][c] = ffma2(a1.u[1], bv, acc[3][c]);
                    }
                }
            }
            #pragma unroll
            for (int c = 0; c < 4; c++) {
                float2 r0 = unpk(acc[0][c]), r1 = unpk(acc[1][c]);
                float2 r2 = unpk(acc[2][c]), r3 = unpk(acc[3][c]);
                float4 lo, hi;
                lo.x = tanha(r0.x); lo.y = tanha(r0.y); lo.z = tanha(r1.x); lo.w = tanha(r1.y);
                hi.x = tanha(r2.x); hi.y = tanha(r2.y); hi.z = tanha(r3.x); hi.w = tanha(r3.y);
                float* p = sH2 + (j0 + c) * 64;
                *(float4*)(p + osH0) = lo;
                *(float4*)(p + osH1) = hi;
            }
        }
        __syncthreads();

        // ---------- GEMM3: h2 @ W3 + Euler-Maruyama ----------
        {
            u64 a3[4][2];
            #pragma unroll
            for (int p = 0; p < 4; p++) { a3[p][0] = bc3[0]; a3[p][1] = bc3[1]; }

            for (int k4 = 0; k4 < 16; ++k4) {
                const int oa0 = ((ty2 + k4) & 15) << 2;
                const int oa1 = ((ty2 + 1 + k4) & 15) << 2;
                const float* arow = sH2 + k4 * 256;
                const float* wrow = sW3d + k4 * 256;
                #pragma unroll
                for (int kk = 0; kk < 4; ++kk) {
                    F4U a0 = ld4(arow + kk * 64 + oa0);
                    F4U a1 = ld4(arow + kk * 64 + oa1);
                    F4U b = ld4(wrow + kk * 64 + 4 * tx);
                    #pragma unroll
                    for (int c = 0; c < 2; c++) {
                        a3[0][c] = ffma2(a0.u[0], b.u[c], a3[0][c]);
                        a3[1][c] = ffma2(a0.u[1], b.u[c], a3[1][c]);
                        a3[2][c] = ffma2(a1.u[0], b.u[c], a3[2][c]);
                        a3[3][c] = ffma2(a1.u[1], b.u[c], a3[3][c]);
                    }
                }
            }

            const u64 dt2 = pk(dtv, dtv);
            const u64 s2  = fmul2(s2base, pk(sq, sq));
            float* orow = out + ((size_t)(t + 1) * BB + base + m0) * D + d0;
            #pragma unroll
            for (int r = 0; r < 8; r++) {
                float2 c0 = unpk(a3[r >> 1][0]);
                float2 c1 = unpk(a3[r >> 1][1]);
                u64 fe = (r & 1) ? pk(c0.y, c1.y) : pk(c0.x, c1.x);
                zp[r] = ffma2(fe, dt2, ffma2(s2, dwv[r], zp[r]));
                *(u64*)(orow + (size_t)r * D) = zp[r];
            }
            // z -> rotated sZ for next step
            #pragma unroll
            for (int c = 0; c < 2; c++) {
                float4 lo, hi;
                if (c == 0) {
                    lo.x = unpk(zp[0]).x; lo.y = unpk(zp[1]).x; lo.z = unpk(zp[2]).x; lo.w = unpk(zp[3]).x;
                    hi.x = unpk(zp[4]).x; hi.y = unpk(zp[5]).x; hi.z = unpk(zp[6]).x; hi.w = unpk(zp[7]).x;
                } else {
                    lo.x = unpk(zp[0]).y; lo.y = unpk(zp[1]).y; lo.z = unpk(zp[2]).y; lo.w = unpk(zp[3]).y;
                    hi.x = unpk(zp[4]).y; hi.y = unpk(zp[5]).y; hi.z = unpk(zp[6]).y; hi.w = unpk(zp[7]).y;
                }
                float* p = sZ + (d0 + c) * 64;
                *(float4*)(p + osZ0) = lo;
                *(float4*)(p + osZ1) = hi;
            }
        }
        __syncthreads();
    }
}

extern "C" void kernel_launch(void* const* d_in, const int* in_sizes, int n_in,
                              void* d_out, int out_size)
{
    (void)in_sizes; (void)n_in; (void)out_size;
    const float* z0     = (const float*)d_in[0];
    const float* ts     = (const float*)d_in[1];
    const float* dW     = (const float*)d_in[2];
    const float* W1     = (const float*)d_in[3];
    const float* b1     = (const float*)d_in[4];
    const float* W2     = (const float*)d_in[5];
    const float* b2     = (const float*)d_in[6];
    const float* W3     = (const float*)d_in[7];
    const float* b3     = (const float*)d_in[8];
    const float* logstd = (const float*)d_in[9];
    float* out = (float*)d_out;

    static bool attr_set = false;  // idempotent attribute; not a work guard
    if (!attr_set) {
        cudaFuncSetAttribute(sde_kernel,
                             cudaFuncAttributeMaxDynamicSharedMemorySize,
                             SMEM_FLOATS * sizeof(float));
        attr_set = true;
    }

    sde_kernel<<<BB / MT, 128, SMEM_FLOATS * sizeof(float)>>>(
        z0, ts, dW, W1, b1, W2, b2, W3, b3, logstd, out);
}